// round 1
// baseline (speedup 1.0000x reference)
#include <cuda_runtime.h>

// SWAP gate on qudits C=0, T=1, DIM=2, WIRES=12 -> D=4096, BATCH=1024.
// The permutation matrix U swaps digit C and digit T of the row index,
// i.e. out[k, b] = x[swap_bits_10_11(k), b]  (involution).
// Output: [2, D, BATCH] float32 (real plane then imag plane).
// Pure bandwidth-bound row-gather; U input is ignored.

#define D_DIM   4096
#define BATCH   1024
#define VEC_PER_ROW (BATCH / 4)          // 256 float4 per row
#define TOTAL_VEC (D_DIM * VEC_PER_ROW)  // 1,048,576 float4 per plane

__global__ void __launch_bounds__(256) swap_gather_kernel(
    const float4* __restrict__ xr,
    const float4* __restrict__ xi,
    float4* __restrict__ out)   // [2, D, BATCH] as float4
{
    unsigned idx = blockIdx.x * blockDim.x + threadIdx.x;  // 0 .. TOTAL_VEC-1
    unsigned row = idx >> 8;          // / VEC_PER_ROW (256)
    unsigned col = idx & 255u;

    // swap bits 10 and 11 of row
    unsigned b10 = (row >> 10) & 1u;
    unsigned b11 = (row >> 11) & 1u;
    unsigned src_row = row ^ ((b10 ^ b11) ? ((1u << 10) | (1u << 11)) : 0u);

    unsigned src = (src_row << 8) | col;

    float4 r = xr[src];
    float4 i = xi[src];
    out[idx] = r;
    out[TOTAL_VEC + idx] = i;
}

extern "C" void kernel_launch(void* const* d_in, const int* in_sizes, int n_in,
                              void* d_out, int out_size) {
    const float4* xr = (const float4*)d_in[0];
    const float4* xi = (const float4*)d_in[1];
    // d_in[2] = U (permutation matrix) — not needed, permutation is closed-form.
    float4* out = (float4*)d_out;

    dim3 grid(TOTAL_VEC / 256);
    dim3 block(256);
    swap_gather_kernel<<<grid, block>>>(xr, xi, out);
}